// round 1
// baseline (speedup 1.0000x reference)
#include <cuda_runtime.h>
#include <math.h>

#define BB 32
#define SS 64
#define EE 256
#define HH 4
#define DD 64
#define TT (BB*SS)   // 2048 tokens

// ---------------- scratch (device globals — no allocation allowed) ----------
__device__ float g_expW[4][EE*EE];   // exp(Wq), exp(Wk), exp(Wv), exp(Wo)
__device__ float g_ex [TT*EE];       // exp(x - m)
__device__ float g_m  [TT];
__device__ float g_q  [TT*EE];
__device__ float g_k  [TT*EE];
__device__ float g_v  [TT*EE];
__device__ float g_att[TT*EE];       // attention output, (B,S,E) layout
__device__ float g_ex2[TT*EE];
__device__ float g_m2 [TT];

// ---------------- kernel 1: exp of all four weight matrices -----------------
__global__ void expw_kernel(const float* __restrict__ Wq,
                            const float* __restrict__ Wk,
                            const float* __restrict__ Wv,
                            const float* __restrict__ Wo)
{
    int i = blockIdx.x * blockDim.x + threadIdx.x;   // 0 .. 4*65536-1
    int w = i >> 16;
    int j = i & 0xFFFF;
    const float* src = (w == 0) ? Wq : (w == 1) ? Wk : (w == 2) ? Wv : Wo;
    g_expW[w][j] = __expf(src[j]);
}

// ---------------- kernel 2: per-token row max + exp(x - m) ------------------
// one block (256 threads) per token
__global__ void rowexp_kernel(const float* __restrict__ X,
                              float* __restrict__ ex,
                              float* __restrict__ m)
{
    int t   = blockIdx.x;
    int tid = threadIdx.x;
    float v = X[t * EE + tid];

    __shared__ float red[8];
    float mx = v;
    #pragma unroll
    for (int o = 16; o > 0; o >>= 1)
        mx = fmaxf(mx, __shfl_xor_sync(0xFFFFFFFFu, mx, o));
    if ((tid & 31) == 0) red[tid >> 5] = mx;
    __syncthreads();
    float bm = red[0];
    #pragma unroll
    for (int i = 1; i < 8; ++i) bm = fmaxf(bm, red[i]);

    ex[t * EE + tid] = __expf(v - bm);
    if (tid == 0) m[t] = bm;
}

// ---------------- LSE matmul tile (shared by qkv and o kernels) -------------
// Y[t,i] = m[t] + log( sum_j A[t,j] * W[i,j] ) + bias[i]
// A: [TT][EE], W: [EE][EE] row-major (out,in), 256 threads, 64x64 block tile.
#define BM 64
#define BN 64
#define BKK 32

__device__ __forceinline__ void lse_mm_tile(
    const float* __restrict__ A,
    const float* __restrict__ W,
    const float* __restrict__ bias,
    const float* __restrict__ m,
    float* __restrict__ Y)
{
    __shared__ float As[BKK][BM + 4];
    __shared__ float Bs[BKK][BN + 4];

    const int tid  = threadIdx.x;
    const int tr   = tid >> 4;      // 0..15
    const int tc   = tid & 15;      // 0..15
    const int row0 = blockIdx.y * BM;
    const int col0 = blockIdx.x * BN;

    float acc[4][4];
    #pragma unroll
    for (int r = 0; r < 4; ++r)
        #pragma unroll
        for (int c = 0; c < 4; ++c) acc[r][c] = 0.f;

    for (int k0 = 0; k0 < EE; k0 += BKK) {
        // load 64x32 tiles of A and W, transposed into smem ([k][row])
        #pragma unroll
        for (int it = 0; it < 8; ++it) {
            int l = it * 256 + tid;
            int r = l >> 5;          // row in tile (0..63)
            int c = l & 31;          // k within tile
            As[c][r] = A[(row0 + r) * EE + k0 + c];
            Bs[c][r] = W[(col0 + r) * EE + k0 + c];
        }
        __syncthreads();

        #pragma unroll
        for (int kk = 0; kk < BKK; ++kk) {
            float4 a = *(const float4*)&As[kk][tr * 4];
            float4 b = *(const float4*)&Bs[kk][tc * 4];
            acc[0][0] += a.x * b.x; acc[0][1] += a.x * b.y;
            acc[0][2] += a.x * b.z; acc[0][3] += a.x * b.w;
            acc[1][0] += a.y * b.x; acc[1][1] += a.y * b.y;
            acc[1][2] += a.y * b.z; acc[1][3] += a.y * b.w;
            acc[2][0] += a.z * b.x; acc[2][1] += a.z * b.y;
            acc[2][2] += a.z * b.z; acc[2][3] += a.z * b.w;
            acc[3][0] += a.w * b.x; acc[3][1] += a.w * b.y;
            acc[3][2] += a.w * b.z; acc[3][3] += a.w * b.w;
        }
        __syncthreads();
    }

    #pragma unroll
    for (int r = 0; r < 4; ++r) {
        int grow = row0 + tr * 4 + r;
        float mr = m[grow];
        #pragma unroll
        for (int c = 0; c < 4; ++c) {
            int gcol = col0 + tc * 4 + c;
            Y[grow * EE + gcol] = mr + __logf(acc[r][c]) + bias[gcol];
        }
    }
}

// fused q/k/v: gridDim.z selects weight / output / bias
__global__ void lse_matmul_qkv(const float* __restrict__ bq,
                               const float* __restrict__ bk,
                               const float* __restrict__ bv)
{
    int z = blockIdx.z;
    const float* W    = g_expW[z];
    float*       Y    = (z == 0) ? g_q : (z == 1) ? g_k : g_v;
    const float* bias = (z == 0) ? bq  : (z == 1) ? bk  : bv;
    lse_mm_tile(g_ex, W, bias, g_m, Y);
}

__global__ void lse_matmul_o(const float* __restrict__ bo,
                             float* __restrict__ out)
{
    lse_mm_tile(g_ex2, g_expW[3], bo, g_m2, out);
}

// ---------------- kernel 4: attention (one block per (b,h)) -----------------
// scores[s,d] = q[b,s,h*D+d] + k[b,s,h*D+d]; softmax over d (64)
// out[s,e]    = sum_d attn[s,d] * v[b, d, h*D+e]   (v's seq index acts as d)
__global__ void attention_kernel()
{
    __shared__ float attn_s[SS][DD + 1];
    __shared__ float v_s   [SS][DD + 1];

    int bh = blockIdx.x;
    int b  = bh / HH;
    int h  = bh % HH;
    int tid = threadIdx.x;          // 256 threads

    // load v tile: v_s[d][e] = g_v[(b*SS + d)*EE + h*DD + e]
    for (int i = tid; i < SS * DD; i += 256) {
        int d = i >> 6, e = i & 63;
        v_s[d][e] = g_v[(b * SS + d) * EE + h * DD + e];
    }

    // softmax: token s handled by 4 consecutive lanes, each covering 16 dims
    int s   = tid >> 2;
    int sub = tid & 3;
    int base = (b * SS + s) * EE + h * DD + sub * 16;

    float sc[16];
    float mx = -1e30f;
    #pragma unroll
    for (int j = 0; j < 16; ++j) {
        sc[j] = g_q[base + j] + g_k[base + j];
        mx = fmaxf(mx, sc[j]);
    }
    mx = fmaxf(mx, __shfl_xor_sync(0xFFFFFFFFu, mx, 1));
    mx = fmaxf(mx, __shfl_xor_sync(0xFFFFFFFFu, mx, 2));

    float sum = 0.f;
    #pragma unroll
    for (int j = 0; j < 16; ++j) { sc[j] = __expf(sc[j] - mx); sum += sc[j]; }
    sum += __shfl_xor_sync(0xFFFFFFFFu, sum, 1);
    sum += __shfl_xor_sync(0xFFFFFFFFu, sum, 2);
    float inv = 1.f / sum;
    #pragma unroll
    for (int j = 0; j < 16; ++j)
        attn_s[s][sub * 16 + j] = sc[j] * inv;

    __syncthreads();

    // out[s][e0..e0+15] = sum_d attn_s[s][d] * v_s[d][e0+j]
    float acc[16];
    #pragma unroll
    for (int j = 0; j < 16; ++j) acc[j] = 0.f;
    int e0 = sub * 16;
    #pragma unroll 8
    for (int d = 0; d < SS; ++d) {
        float a = attn_s[s][d];
        #pragma unroll
        for (int j = 0; j < 16; ++j)
            acc[j] += a * v_s[d][e0 + j];
    }
    int obase = (b * SS + s) * EE + h * DD + e0;
    #pragma unroll
    for (int j = 0; j < 16; ++j)
        g_att[obase + j] = acc[j];
}

// ---------------- launcher ---------------------------------------------------
extern "C" void kernel_launch(void* const* d_in, const int* in_sizes, int n_in,
                              void* d_out, int out_size)
{
    const float* x  = (const float*)d_in[0];
    const float* Wq = (const float*)d_in[1];
    const float* bq = (const float*)d_in[2];
    const float* Wk = (const float*)d_in[3];
    const float* bk = (const float*)d_in[4];
    const float* Wv = (const float*)d_in[5];
    const float* bv = (const float*)d_in[6];
    const float* Wo = (const float*)d_in[7];
    const float* bo = (const float*)d_in[8];
    float* out = (float*)d_out;

    float *g_ex_p, *g_m_p, *g_att_p, *g_ex2_p, *g_m2_p;
    cudaGetSymbolAddress((void**)&g_ex_p,  g_ex);
    cudaGetSymbolAddress((void**)&g_m_p,   g_m);
    cudaGetSymbolAddress((void**)&g_att_p, g_att);
    cudaGetSymbolAddress((void**)&g_ex2_p, g_ex2);
    cudaGetSymbolAddress((void**)&g_m2_p,  g_m2);

    // 1. exp(W) for all four weight matrices
    expw_kernel<<<(4 * EE * EE) / 256, 256>>>(Wq, Wk, Wv, Wo);

    // 2. per-token max + exp(x - m)
    rowexp_kernel<<<TT, 256>>>(x, g_ex_p, g_m_p);

    // 3. q,k,v = m + log(ex @ expW^T) + b   (fused, gridDim.z = 3)
    {
        dim3 grid(EE / BN, TT / BM, 3);
        lse_matmul_qkv<<<grid, 256>>>(bq, bk, bv);
    }

    // 4. attention: softmax(q+k) @ v per (b,h)
    attention_kernel<<<BB * HH, 256>>>();

    // 5. per-token max + exp on attention output
    rowexp_kernel<<<TT, 256>>>(g_att_p, g_ex2_p, g_m2_p);

    // 6. final tropical linear -> d_out
    {
        dim3 grid(EE / BN, TT / BM, 1);
        lse_matmul_o<<<grid, 256>>>(bo, out);
    }
}